// round 9
// baseline (speedup 1.0000x reference)
#include <cuda_runtime.h>

#define TT 128
#define BB 512
#define EE 128
#define NEVT 16
#define NB 2
#define NBLK (BB / NB)
#define L2E 1.4426950408889634f
#define LN2 0.6931471805599453f
#define PSTR 168   // floats per batch slot: 16 chunks * 10 + pad

__device__ float g_partial[BB];
__device__ unsigned int g_done;   // zero-init; restored to 0 each launch

typedef unsigned long long ull;

// ---------------------------------------------------------------------------
__device__ __forceinline__ void ffma2(ull &d, ull a, ull b) {
    asm("fma.rn.f32x2 %0, %1, %2, %0;" : "+l"(d) : "l"(a), "l"(b));
}
__device__ __forceinline__ void fadd2(ull &d, ull a) {
    asm("add.rn.f32x2 %0, %0, %1;" : "+l"(d) : "l"(a));
}
__device__ __forceinline__ ull pack2(float lo, float hi) {
    ull r; asm("mov.b64 %0, {%1, %2};" : "=l"(r) : "f"(lo), "f"(hi)); return r;
}
__device__ __forceinline__ float pairsum(ull a) {
    float lo, hi; asm("mov.b64 {%0, %1}, %2;" : "=f"(lo), "=f"(hi) : "l"(a));
    return lo + hi;
}
__device__ __forceinline__ float ex2(float x) {
    float r; asm("ex2.approx.ftz.f32 %0, %1;" : "=f"(r) : "f"(x)); return r;
}
__device__ __forceinline__ float lg2(float x) {
    float r; asm("lg2.approx.ftz.f32 %0, %1;" : "=f"(r) : "f"(x)); return r;
}

// ---------------------------------------------------------------------------
// 256 threads: thread (g = tid>>4, c = tid&15) holds Q rows {g+16m, m=0..7}
// restricted to k in [8c, 8c+8) -- 64 floats of Q in registers (R=8 reuse).
// Matvec: 8 LDS.64 of P feed 64 FFMA2 (1B/FFMA2 of smem return traffic; the
// R8 profile proved per-lane return bandwidth at 128B/cy/SM is the binding
// pipe). 15 selected-operand SHFLs route full sums so each thread ends with
// ONE (row=g+16*(c&7), batch=c>>3) state. Lagged normalizer G (lag 3, 3-slot
// race-free rotation) keeps lse exact with no reduction on the critical path.
// ---------------------------------------------------------------------------
__global__ void __launch_bounds__(256, 2)
crf_kernel(const float* __restrict__ feats, const float* __restrict__ trans,
           float* __restrict__ out, int nblocks) {
    const int tid = threadIdx.x;
    const int g = tid >> 4, c = tid & 15;
    const int myb = c >> 3, mr = c & 7;
    const int jown = g + 16 * mr;
    const int lane = tid & 31, wrp = tid >> 5;     // 8 warps
    const int b0 = blockIdx.x * NB;
    const int cb2 = (c >> 2) & 1, cb1 = (c >> 1) & 1, cb0 = c & 1;

    __shared__ __align__(16) float PQ[2][NB * PSTR];
    __shared__ __align__(16) float wmbuf[3][NB][8];   // 3-slot rotation
    __shared__ float bmv[NB][NEVT][8], bsv[NB][NEVT][8];
    __shared__ float rsum[8];
    __shared__ unsigned s_last;

    // ---- feat prefetch first (long latency): (jown, b0+myb) ----
    const size_t bstr = (size_t)BB * EE;
    const float* fp = feats + (size_t)(b0 + myb) * EE + jown;
    float fA  = fp[bstr];       // t=1 (u=0)
    float fn  = fp[2 * bstr];   // t=2 (u=1)
    float fn2 = 0.0f;

    // ---- build q: 8 rows x my 8-k chunk, log2 domain ----
    float mt[8];
#pragma unroll
    for (int m = 0; m < 8; m++) {
        const float4* rp = (const float4*)(trans + (g + 16 * m) * EE + 8 * c);
        float4 a = rp[0], bq = rp[1];
        mt[m] = fmaxf(fmaxf(fmaxf(a.x, a.y), fmaxf(a.z, a.w)),
                      fmaxf(fmaxf(bq.x, bq.y), fmaxf(bq.z, bq.w)));
    }
#pragma unroll
    for (int o = 1; o <= 8; o <<= 1)
#pragma unroll
        for (int m = 0; m < 8; m++)
            mt[m] = fmaxf(mt[m], __shfl_xor_sync(0xffffffffu, mt[m], o));
    ull q[8][4];
#pragma unroll
    for (int m = 0; m < 8; m++) {
        const float4* rp = (const float4*)(trans + (g + 16 * m) * EE + 8 * c);
        float4 a = rp[0], bq = rp[1];   // L1 hit (second pass)
        q[m][0] = pack2(ex2((a.x - mt[m]) * L2E), ex2((a.y - mt[m]) * L2E));
        q[m][1] = pack2(ex2((a.z - mt[m]) * L2E), ex2((a.w - mt[m]) * L2E));
        q[m][2] = pack2(ex2((bq.x - mt[m]) * L2E), ex2((bq.y - mt[m]) * L2E));
        q[m][3] = pack2(ex2((bq.z - mt[m]) * L2E), ex2((bq.w - mt[m]) * L2E));
    }
    const float mtown = mt[mr] * L2E;
    const float tl2 = trans[(EE - 1) * EE + jown] * L2E;  // transitions[-1][jown]

    float Gu  = (b0 + myb == 0) ? 0.0f : (-10000.0f * L2E);
    float Gm1 = Gu;
    if (tid < 48) {   // init all 3 slots x 2 b x 8 warps with per-b init fv
        int sl = tid >> 4, bb = (tid >> 3) & 1, w = tid & 7;
        wmbuf[sl][bb][w] = (b0 + bb == 0) ? 0.0f : (-10000.0f * L2E);
    }

    float P = ex2(fA * L2E);    // u=0: fv_init uniform == G per batch
    float ly = 0.0f, ec = 0.0f;
    int t2 = 3, s2 = 2;         // prefetch: t(u+2), (u+2) mod 7
    int rsl = 1, wsl = 2;       // read slot (u+1)%3, write slot (u+2)%3
    const int stidx = myb * PSTR + 10 * (jown >> 3) + (jown & 7);

#pragma unroll 1
    for (int u = 0; u < 112; u++) {
        PQ[u & 1][stidx] = P;
        __syncthreads();

        // ---- shadow work (off critical path) ----
        float Gn;
        {
            float4 w0 = *(const float4*)&wmbuf[rsl][myb][0];
            float4 w1 = *(const float4*)&wmbuf[rsl][myb][4];
            Gn = fmaxf(fmaxf(fmaxf(w0.x, w0.y), fmaxf(w0.z, w0.w)),
                       fmaxf(fmaxf(w1.x, w1.y), fmaxf(w1.z, w1.w)));
        }
        if (u >= 1) {
            float fvp = Gm1 + mtown + ly;       // lazy fv_{u-1}
            float wm = fvp;                     // max over my b's 16 rows in warp
            wm = fmaxf(wm, __shfl_xor_sync(0xffffffffu, wm, 1));
            wm = fmaxf(wm, __shfl_xor_sync(0xffffffffu, wm, 2));
            wm = fmaxf(wm, __shfl_xor_sync(0xffffffffu, wm, 4));
            wm = fmaxf(wm, __shfl_xor_sync(0xffffffffu, wm, 16));
            if (mr == 0) wmbuf[wsl][myb][wrp] = wm;
            if ((u % 7) == 0) {                 // boundary e = u/7-1 (u=7..105)
                int e = u / 7 - 1;
                float v = fvp + tl2;
                float mm = v;
                mm = fmaxf(mm, __shfl_xor_sync(0xffffffffu, mm, 1));
                mm = fmaxf(mm, __shfl_xor_sync(0xffffffffu, mm, 2));
                mm = fmaxf(mm, __shfl_xor_sync(0xffffffffu, mm, 4));
                mm = fmaxf(mm, __shfl_xor_sync(0xffffffffu, mm, 16));
                float ss = ex2(v - mm);
                ss += __shfl_xor_sync(0xffffffffu, ss, 1);
                ss += __shfl_xor_sync(0xffffffffu, ss, 2);
                ss += __shfl_xor_sync(0xffffffffu, ss, 4);
                ss += __shfl_xor_sync(0xffffffffu, ss, 16);
                if (mr == 0) { bmv[myb][e][wrp] = mm; bsv[myb][e][wrp] = ss; }
            }
        }
        ec = ex2(fmaf(fn, L2E, Gu + mtown - Gn));    // for step u+1
        if (u < 110) fn2 = fp[(size_t)t2 * bstr];    // f_{u+2}
        s2++; if (s2 == 7) { s2 = 0; t2 += 2; } else t2++;

        // ---- matvec: 8 rows x 2 batches, k in [8c, 8c+8) ----
        const ull* P0 = (const ull*)(PQ[u & 1] + 10 * c);
        const ull* P1 = (const ull*)(PQ[u & 1] + PSTR + 10 * c);
        ull k0a = P0[0], k0b = P0[1], k0c = P0[2], k0d = P0[3];
        ull k1a = P1[0], k1b = P1[1], k1c = P1[2], k1d = P1[3];
        float pv0[8], pv1[8];
#pragma unroll
        for (int m = 0; m < 8; m++) {
            ull A = 0, Bq = 0;
            ffma2(A, q[m][0], k0a); ffma2(Bq, q[m][1], k0b);
            ffma2(A, q[m][2], k0c); ffma2(Bq, q[m][3], k0d);
            fadd2(A, Bq);
            pv0[m] = pairsum(A);
        }
#pragma unroll
        for (int m = 0; m < 8; m++) {
            ull A = 0, Bq = 0;
            ffma2(A, q[m][0], k1a); ffma2(Bq, q[m][1], k1b);
            ffma2(A, q[m][2], k1c); ffma2(Bq, q[m][3], k1d);
            fadd2(A, Bq);
            pv1[m] = pairsum(A);
        }

        // ---- combine across the 16 k-chunks (selected-operand butterfly) ----
        float v8[8];
#pragma unroll
        for (int m = 0; m < 8; m++) {       // xor 8: resolve batch
            float s = myb ? pv0[m] : pv1[m];
            float rv = __shfl_xor_sync(0xffffffffu, s, 8);
            v8[m] = (myb ? pv1[m] : pv0[m]) + rv;
        }
        float v4[4];
#pragma unroll
        for (int i = 0; i < 4; i++) {       // xor 4: resolve row bit2
            float s = cb2 ? v8[i] : v8[4 + i];
            float rv = __shfl_xor_sync(0xffffffffu, s, 4);
            v4[i] = v8[cb2 * 4 + i] + rv;
        }
        float v2[2];
#pragma unroll
        for (int i = 0; i < 2; i++) {       // xor 2: resolve row bit1
            float s = cb1 ? v4[i] : v4[2 + i];
            float rv = __shfl_xor_sync(0xffffffffu, s, 2);
            v2[i] = v4[cb1 * 2 + i] + rv;
        }
        float s1 = cb0 ? v2[0] : v2[1];     // xor 1: resolve row bit0
        float rv1 = __shfl_xor_sync(0xffffffffu, s1, 1);
        float y = v2[cb0] + rv1;

        P  = y * ec;
        ly = lg2(y);
        Gm1 = Gu; Gu = Gn; fn = fn2;
        rsl++; if (rsl == 3) rsl = 0;
        wsl++; if (wsl == 3) wsl = 0;
    }

    // terminal partials from fv_111 = Gm1 + mtown + ly
    {
        float v = Gm1 + mtown + ly + tl2;
        float mm = v;
        mm = fmaxf(mm, __shfl_xor_sync(0xffffffffu, mm, 1));
        mm = fmaxf(mm, __shfl_xor_sync(0xffffffffu, mm, 2));
        mm = fmaxf(mm, __shfl_xor_sync(0xffffffffu, mm, 4));
        mm = fmaxf(mm, __shfl_xor_sync(0xffffffffu, mm, 16));
        float ss = ex2(v - mm);
        ss += __shfl_xor_sync(0xffffffffu, ss, 1);
        ss += __shfl_xor_sync(0xffffffffu, ss, 2);
        ss += __shfl_xor_sync(0xffffffffu, ss, 4);
        ss += __shfl_xor_sync(0xffffffffu, ss, 16);
        if (mr == 0) { bmv[myb][NEVT - 1][wrp] = mm; bsv[myb][NEVT - 1][wrp] = ss; }
    }
    __syncthreads();

    // combine deferred partials: 32 threads = 16 events x 2 batches
    if (tid < 32) {
        int ev = tid & 15, bt = tid >> 4;
        float M = -3.4e38f;
#pragma unroll
        for (int w = 0; w < 8; w++) M = fmaxf(M, bmv[bt][ev][w]);
        float ss = 0.0f;
#pragma unroll
        for (int w = 0; w < 8; w++) ss += bsv[bt][ev][w] * ex2(bmv[bt][ev][w] - M);
        float l = M + lg2(ss);              // per-event lse, log2 units
#pragma unroll
        for (int o = 1; o < 16; o <<= 1) l += __shfl_xor_sync(0xffffffffu, l, o);
        if (ev == 0) g_partial[b0 + bt] = l * LN2;
    }

    // ---- fused final reduction: last block sums all partials ----
    __threadfence();
    __syncthreads();
    if (tid == 0) {
        unsigned v = atomicAdd(&g_done, 1u);
        s_last = (v == (unsigned)(nblocks - 1)) ? 1u : 0u;
    }
    __syncthreads();
    if (s_last) {
        __threadfence();
        float v = __ldcg(&g_partial[tid]) + __ldcg(&g_partial[tid + 256]);
#pragma unroll
        for (int o = 16; o; o >>= 1) v += __shfl_xor_sync(0xffffffffu, v, o);
        if (lane == 0) rsum[wrp] = v;
        __syncthreads();
        if (tid == 0) {
            float tot = 0.0f;
#pragma unroll
            for (int w = 0; w < 8; w++) tot += rsum[w];
            out[0] = tot * (1.0f / (float)(BB * NEVT));
            g_done = 0;                     // restore for next graph replay
        }
    }
}

// ---------------------------------------------------------------------------
extern "C" void kernel_launch(void* const* d_in, const int* in_sizes, int n_in,
                              void* d_out, int out_size) {
    const float* feats = (const float*)d_in[0];
    const float* trans = (const float*)d_in[1];
    if (n_in >= 2 && in_sizes[0] == EE * EE) {   // defensive order check
        feats = (const float*)d_in[1];
        trans = (const float*)d_in[0];
    }
    crf_kernel<<<NBLK, 256>>>(feats, trans, (float*)d_out, NBLK);
}

// round 12
// speedup vs baseline: 1.9271x; 1.9271x over previous
#include <cuda_runtime.h>
#include <cstdint>

#define TT 128
#define BB 512
#define EE 128
#define NEVT 16
#define NBC 8               // batches per CTA
#define NBLK (BB / NBC)     // 64 CTAs
#define L2E 1.4426950408889634f
#define LN2 0.6931471805599453f
#define NEGL2 (-10000.0f * L2E)

__device__ float g_partial[BB];
__device__ unsigned g_done;     // zero-init; restored each launch

// ---------------------------------------------------------------------------
__device__ __forceinline__ float ex2(float x) {
    float r; asm("ex2.approx.ftz.f32 %0, %1;" : "=f"(r) : "f"(x)); return r;
}
__device__ __forceinline__ float lg2(float x) {
    float r; asm("lg2.approx.ftz.f32 %0, %1;" : "=f"(r) : "f"(x)); return r;
}
__device__ __forceinline__ uint32_t totf32(float x) {   // round-to-nearest tf32
    uint32_t r; asm("cvt.rna.tf32.f32 %0, %1;" : "=r"(r) : "f"(x)); return r;
}
// m16n8k8 tf32 HMMA (baseline sm_80+ feature; works on plain sm_103 target)
__device__ __forceinline__ void mma8(float& c0, float& c1, float& c2, float& c3,
                                     uint32_t a0, uint32_t a1, uint32_t a2,
                                     uint32_t a3, uint32_t b0, uint32_t b1) {
    asm volatile(
        "mma.sync.aligned.m16n8k8.row.col.f32.tf32.tf32.f32 "
        "{%0,%1,%2,%3}, {%4,%5,%6,%7}, {%8,%9}, {%0,%1,%2,%3};"
        : "+f"(c0), "+f"(c1), "+f"(c2), "+f"(c3)
        : "r"(a0), "r"(a1), "r"(a2), "r"(a3), "r"(b0), "r"(b1));
}

// ---------------------------------------------------------------------------
// Per step: Y[128x8] = Q[128x128] @ P[128x8] via 16 chained m16n8k8 tf32 MMAs
// per warp (warp w owns rows 16w..16w+15; C-fragment cols = the 8 batches).
// Q is STATIONARY in registers as A-fragments. P routed through smem
// (conflict-free), double buffered, ONE barrier per step, zero shuffles on the
// critical path. Normalizer G(b) = fv[row 17][b] lagged 2 steps (3-slot
// rotation) -> exact lse, no reductions in the loop. Boundary lse partials
// are y * 2^(mt+tl) (no lg2), combined after the loop.
// ---------------------------------------------------------------------------
__global__ void __launch_bounds__(256)
crf_kernel(const float* __restrict__ feats, const float* __restrict__ trans,
           float* __restrict__ out, int nblocks) {
    const int tid = threadIdx.x;
    const int w = tid >> 5, lane = tid & 31;
    const int g = lane >> 2, tig = lane & 3;
    const int r0 = 16 * w + g, r1 = r0 + 8;
    const int bA = 2 * tig, bB = bA + 1;
    const int b0 = blockIdx.x * NBC;

    __shared__ __align__(16) float Pbuf[2][EE * NBC];   // [j*8 + b]
    __shared__ float slot[3][NBC];                      // G rotation
    __shared__ float bwp[NEVT][8][NBC];                 // boundary partials
    __shared__ float gsv[NEVT][NBC];                    // Gc at each event
    __shared__ float mt2s[EE], tl2s[EE];
    __shared__ float rsum[8];
    __shared__ unsigned slast;

    // ---- feat prefetch pointers (combo order: (r0,bA),(r0,bB),(r1,bA),(r1,bB))
    const size_t tstr = (size_t)BB * EE;
    const float* fpp[4];
    fpp[0] = feats + (size_t)(b0 + bA) * EE + r0;
    fpp[1] = feats + (size_t)(b0 + bB) * EE + r0;
    fpp[2] = fpp[0] + 8;
    fpp[3] = fpp[1] + 8;
    float f1[4], fcur[4], fnx[4], fnew[4];
#pragma unroll
    for (int i = 0; i < 4; i++) f1[i]   = fpp[i][tstr];        // t=1
#pragma unroll
    for (int i = 0; i < 4; i++) fcur[i] = fpp[i][2 * tstr];    // t=2
#pragma unroll
    for (int i = 0; i < 4; i++) fnx[i]  = fpp[i][3 * tstr];    // t=3
#pragma unroll
    for (int i = 0; i < 4; i++) fnew[i] = fnx[i];

    // ---- row maxes + last-row transitions (log2 units) ----
    if (tid < EE) {
        const float4* rp = (const float4*)(trans + tid * EE);
        float m = -3.4e38f;
#pragma unroll
        for (int i = 0; i < 32; i++) {
            float4 v = rp[i];
            m = fmaxf(m, fmaxf(fmaxf(v.x, v.y), fmaxf(v.z, v.w)));
        }
        mt2s[tid] = m * L2E;
        tl2s[tid] = trans[(EE - 1) * EE + tid] * L2E;
    }
    if (tid < NBC)      // preinit G slot[2] (= G_1 = fv_init)
        slot[2][tid] = (b0 + tid == 0) ? 0.0f : NEGL2;
    __syncthreads();

    const float mtA = mt2s[r0], mtB = mt2s[r1];
    const float etlA = ex2(mtA + tl2s[r0]);   // 2^(mt+tl) per owned row
    const float etlB = ex2(mtB + tl2s[r1]);

    // ---- build stationary A fragments: Q rows r0,r1 (log2 domain, tf32) ----
    uint32_t a[16][4];
#pragma unroll
    for (int s = 0; s < 16; s++) {
        int k0 = 8 * s + tig, k2 = k0 + 4;
        a[s][0] = totf32(ex2(fmaf(trans[r0 * EE + k0], L2E, -mtA)));
        a[s][1] = totf32(ex2(fmaf(trans[r1 * EE + k0], L2E, -mtB)));
        a[s][2] = totf32(ex2(fmaf(trans[r0 * EE + k2], L2E, -mtA)));
        a[s][3] = totf32(ex2(fmaf(trans[r1 * EE + k2], L2E, -mtB)));
    }

    float Gc[2];
    Gc[0] = (b0 + bA == 0) ? 0.0f : NEGL2;
    Gc[1] = NEGL2;                      // b0+bB >= 1 always

    // P_0 = 2^(f(t=1)*L2E)  (fv_init uniform per batch == G_0)
    Pbuf[0][r0 * 8 + bA] = ex2(f1[0] * L2E);
    Pbuf[0][r0 * 8 + bB] = ex2(f1[1] * L2E);
    Pbuf[0][r1 * 8 + bA] = ex2(f1[2] * L2E);
    Pbuf[0][r1 * 8 + bB] = ex2(f1[3] * L2E);
    __syncthreads();

#pragma unroll 1
    for (int u = 0; u < 112; u++) {
        // ---- shadow: normalizer + ec for P_{u+1}, feat prefetch ----
        const int ri = (u + 2) % 3;
        float Gn0 = slot[ri][bA], Gn1 = slot[ri][bB];
        float ec[4];
        ec[0] = ex2(fmaf(fcur[0], L2E, Gc[0] + mtA - Gn0));
        ec[1] = ex2(fmaf(fcur[1], L2E, Gc[1] + mtA - Gn1));
        ec[2] = ex2(fmaf(fcur[2], L2E, Gc[0] + mtB - Gn0));
        ec[3] = ex2(fmaf(fcur[3], L2E, Gc[1] + mtB - Gn1));
        if (u <= 108) {
            size_t off = (size_t)(u + 4 + (u + 3) / 7) * tstr;   // t(u+3)
#pragma unroll
            for (int i = 0; i < 4; i++) fnew[i] = fpp[i][off];
        }

        // ---- tensor matvec: 16 HMMA, 4 independent accumulator chains ----
        const float* PB = Pbuf[u & 1];
        float c[4][4];
#pragma unroll
        for (int q = 0; q < 4; q++)
#pragma unroll
            for (int i = 0; i < 4; i++) c[q][i] = 0.0f;
#pragma unroll
        for (int s = 0; s < 16; s++) {
            uint32_t bv0 = __float_as_uint(PB[(8 * s + tig) * 8 + g]);
            uint32_t bv1 = __float_as_uint(PB[(8 * s + tig + 4) * 8 + g]);
            mma8(c[s & 3][0], c[s & 3][1], c[s & 3][2], c[s & 3][3],
                 a[s][0], a[s][1], a[s][2], a[s][3], bv0, bv1);
        }
        float y0 = (c[0][0] + c[1][0]) + (c[2][0] + c[3][0]);  // (r0,bA)
        float y1 = (c[0][1] + c[1][1]) + (c[2][1] + c[3][1]);  // (r0,bB)
        float y2 = (c[0][2] + c[1][2]) + (c[2][2] + c[3][2]);  // (r1,bA)
        float y3 = (c[0][3] + c[1][3]) + (c[2][3] + c[3][3]);  // (r1,bB)

        // ---- P_{u+1} = y * ec ----
        if (u < 111) {
            float* PW = Pbuf[(u + 1) & 1];
            *(float2*)&PW[r0 * 8 + bA] = make_float2(y0 * ec[0], y1 * ec[1]);
            *(float2*)&PW[r1 * 8 + bA] = make_float2(y2 * ec[2], y3 * ec[3]);
        }

        // ---- publish G (row 17 = warp 1, g==1, r0 path) ----
        if (w == 1 && g == 1) {
            slot[u % 3][bA] = Gc[0] + mtA + lg2(y0);
            slot[u % 3][bB] = Gc[1] + mtA + lg2(y1);
        }

        // ---- boundary lse partials (every 7th step, e = u/7) ----
        if ((u % 7) == 6) {
            int e = u / 7;
            float sA = fmaf(y0, etlA, y2 * etlB);   // batch bA: 2^(fv+tl-Gc)
            float sB = fmaf(y1, etlA, y3 * etlB);   // batch bB
            sA += __shfl_xor_sync(0xffffffffu, sA, 4);
            sB += __shfl_xor_sync(0xffffffffu, sB, 4);
            sA += __shfl_xor_sync(0xffffffffu, sA, 8);
            sB += __shfl_xor_sync(0xffffffffu, sB, 8);
            sA += __shfl_xor_sync(0xffffffffu, sA, 16);
            sB += __shfl_xor_sync(0xffffffffu, sB, 16);
            if (lane < 4) {             // lane == tig here
                bwp[e][w][bA] = sA;
                bwp[e][w][bB] = sB;
                if (w == 0) { gsv[e][bA] = Gc[0]; gsv[e][bB] = Gc[1]; }
            }
        }

        __syncthreads();
        Gc[0] = Gn0; Gc[1] = Gn1;
#pragma unroll
        for (int i = 0; i < 4; i++) { fcur[i] = fnx[i]; fnx[i] = fnew[i]; }
    }

    // ---- combine 16 events x 8 batches ----
    if (tid < 128) {
        int e = tid & 15, b = tid >> 4;
        float s8 = 0.0f;
#pragma unroll
        for (int ww = 0; ww < 8; ww++) s8 += bwp[e][ww][b];
        float val = gsv[e][b] + lg2(s8);
#pragma unroll
        for (int o = 1; o < 16; o <<= 1)
            val += __shfl_xor_sync(0xffffffffu, val, o);
        if (e == 0) g_partial[b0 + b] = val * LN2;
    }

    // ---- fused final reduction (last CTA) ----
    __threadfence();
    __syncthreads();
    if (tid == 0) {
        unsigned v = atomicAdd(&g_done, 1u);
        slast = (v == (unsigned)(nblocks - 1)) ? 1u : 0u;
    }
    __syncthreads();
    if (slast) {
        __threadfence();
        float v = __ldcg(&g_partial[tid]) + __ldcg(&g_partial[tid + 256]);
#pragma unroll
        for (int o = 16; o; o >>= 1) v += __shfl_xor_sync(0xffffffffu, v, o);
        if (lane == 0) rsum[w] = v;
        __syncthreads();
        if (tid == 0) {
            float tot = 0.0f;
#pragma unroll
            for (int ww = 0; ww < 8; ww++) tot += rsum[ww];
            out[0] = tot * (1.0f / (float)(BB * NEVT));
            g_done = 0;                 // restore for next graph replay
        }
    }
}

// ---------------------------------------------------------------------------
extern "C" void kernel_launch(void* const* d_in, const int* in_sizes, int n_in,
                              void* d_out, int out_size) {
    const float* feats = (const float*)d_in[0];
    const float* trans = (const float*)d_in[1];
    if (n_in >= 2 && in_sizes[0] == EE * EE) {   // defensive order check
        feats = (const float*)d_in[1];
        trans = (const float*)d_in[0];
    }
    crf_kernel<<<NBLK, 256>>>(feats, trans, (float*)d_out, NBLK);
}